// round 2
// baseline (speedup 1.0000x reference)
#include <cuda_runtime.h>
#include <math.h>

#define BSZ 4
#define CDIM 512
#define NN 4096
#define MM 4096
#define DAD 128

// ---------------- scratch (device globals; no allocation) ----------------
__device__ float g_q[BSZ * DAD * NN];       // [B,128,4096]
__device__ float g_kmat[BSZ * DAD * MM];    // [B,128,4096]
__device__ float g_v[BSZ * CDIM * MM];      // [B,512,4096]
__device__ float g_e[67108864];             // [B,4096,4096] = 256 MB
__device__ float g_o[BSZ * NN * CDIM];      // [B,4096,512]
__device__ float g_inv[CDIM];
__device__ float g_cadd[CDIM];

// ---------------- BN-fold precompute ----------------
__global__ void precomp_k(const float* __restrict__ gamma,
                          const float* __restrict__ beta,
                          const float* __restrict__ rmean,
                          const float* __restrict__ rvar,
                          const float* __restrict__ b_t) {
    int c = threadIdx.x;
    if (c < CDIM) {
        float inv = gamma[c] * rsqrtf(rvar[c] + 1e-5f);
        g_inv[c]  = inv;
        g_cadd[c] = b_t[c] * inv + beta[c] - rmean[c] * inv;
    }
}

// ---------------- generic 128x128x8 fp32 SGEMM ----------------
// C[m,n] = epi( alpha * sum_k A[m,k]*B[k,n] )
// TA: A given as raw [K, M] row-major (lda=M). else raw [M, K] (lda=K).
// TB: B given as raw [N, K] row-major (ldb=K). else raw [K, N] (ldb=N).
// EPI: 0 = *alpha ; 1 = +biasRow[m] ; 2 = relu(val*scaleCol[n]+addCol[n])
template <int TA, int TB, int EPI>
__global__ __launch_bounds__(256)
void sgemm_k(const float* __restrict__ A, const float* __restrict__ B,
             float* __restrict__ C,
             int Mdim, int Ndim, int Kdim,
             long long sA, long long sB, long long sC,
             float alpha,
             const float* __restrict__ biasRow,
             const float* __restrict__ scaleCol,
             const float* __restrict__ addCol) {
    __shared__ float As[8][128];
    __shared__ float Bs[8][128];

    A += (long long)blockIdx.z * sA;
    B += (long long)blockIdx.z * sB;
    C += (long long)blockIdx.z * sC;

    const int row0 = blockIdx.y * 128;
    const int col0 = blockIdx.x * 128;
    const int t = threadIdx.x;
    const int lda = TA ? Mdim : Kdim;
    const int ldb = TB ? Kdim : Ndim;
    const int rm = (t >> 4) * 8;
    const int rn = (t & 15) * 8;

    float acc[8][8];
#pragma unroll
    for (int i = 0; i < 8; i++)
#pragma unroll
        for (int j = 0; j < 8; j++) acc[i][j] = 0.f;

    for (int k0 = 0; k0 < Kdim; k0 += 8) {
        // ---- stage A tile into As[k][m] ----
        if (TA) {
            int ar = t >> 5;            // k 0..7
            int ac = (t & 31) * 4;      // m 0..124
            float4 v = *(const float4*)(A + (long long)(k0 + ar) * lda + row0 + ac);
            *(float4*)&As[ar][ac] = v;
        } else {
            int ar = t >> 1;            // m 0..127
            int ac = (t & 1) * 4;       // k 0 or 4
            float4 v = *(const float4*)(A + (long long)(row0 + ar) * lda + k0 + ac);
            As[ac + 0][ar] = v.x;
            As[ac + 1][ar] = v.y;
            As[ac + 2][ar] = v.z;
            As[ac + 3][ar] = v.w;
        }
        // ---- stage B tile into Bs[k][n] ----
        if (TB) {
            int br = t >> 1;            // n 0..127
            int bc = (t & 1) * 4;       // k 0 or 4
            float4 v = *(const float4*)(B + (long long)(col0 + br) * ldb + k0 + bc);
            Bs[bc + 0][br] = v.x;
            Bs[bc + 1][br] = v.y;
            Bs[bc + 2][br] = v.z;
            Bs[bc + 3][br] = v.w;
        } else {
            int br = t >> 5;            // k 0..7
            int bc = (t & 31) * 4;      // n 0..124
            float4 v = *(const float4*)(B + (long long)(k0 + br) * ldb + col0 + bc);
            *(float4*)&Bs[br][bc] = v;
        }
        __syncthreads();

#pragma unroll
        for (int kk = 0; kk < 8; kk++) {
            float a[8], b[8];
            *(float4*)(a)     = *(float4*)&As[kk][rm];
            *(float4*)(a + 4) = *(float4*)&As[kk][rm + 4];
            *(float4*)(b)     = *(float4*)&Bs[kk][rn];
            *(float4*)(b + 4) = *(float4*)&Bs[kk][rn + 4];
#pragma unroll
            for (int i = 0; i < 8; i++)
#pragma unroll
                for (int j = 0; j < 8; j++) acc[i][j] += a[i] * b[j];
        }
        __syncthreads();
    }

    // ---- epilogue ----
    float sc[8], ad[8];
    if (EPI == 2) {
#pragma unroll
        for (int j = 0; j < 8; j++) {
            sc[j] = scaleCol[col0 + rn + j];
            ad[j] = addCol[col0 + rn + j];
        }
    }
#pragma unroll
    for (int i = 0; i < 8; i++) {
        int r = row0 + rm + i;
        float bb = (EPI == 1) ? biasRow[r] : 0.f;
        float ov[8];
#pragma unroll
        for (int j = 0; j < 8; j++) {
            float val = acc[i][j];
            if (EPI == 0) val *= alpha;
            else if (EPI == 1) val += bb;
            else val = fmaxf(fmaf(val, sc[j], ad[j]), 0.f);
            ov[j] = val;
        }
        float4* dst = (float4*)(C + (long long)r * Ndim + col0 + rn);
        dst[0] = make_float4(ov[0], ov[1], ov[2], ov[3]);
        dst[1] = make_float4(ov[4], ov[5], ov[6], ov[7]);
    }
}

// ---------------- row softmax over 4096 (in place) ----------------
__inline__ __device__ float warpRedMax(float v) {
#pragma unroll
    for (int o = 16; o; o >>= 1) v = fmaxf(v, __shfl_xor_sync(0xFFFFFFFFu, v, o));
    return v;
}
__inline__ __device__ float warpRedSum(float v) {
#pragma unroll
    for (int o = 16; o; o >>= 1) v += __shfl_xor_sync(0xFFFFFFFFu, v, o);
    return v;
}

__global__ __launch_bounds__(256) void softmax_k(float* __restrict__ e) {
    __shared__ float red[8];
    size_t row = blockIdx.x;
    float4* p = (float4*)(e + row * 4096);
    int t = threadIdx.x;
    int wid = t >> 5, lid = t & 31;

    float4 v[4];
    float mx = -1e30f;
#pragma unroll
    for (int i = 0; i < 4; i++) {
        v[i] = p[t + i * 256];
        mx = fmaxf(mx, fmaxf(fmaxf(v[i].x, v[i].y), fmaxf(v[i].z, v[i].w)));
    }
    mx = warpRedMax(mx);
    if (lid == 0) red[wid] = mx;
    __syncthreads();
    // FIX: only lanes 0..7 contribute valid partials; others use identity
    mx = (lid < 8) ? red[lid] : -1e30f;
    mx = warpRedMax(mx);

    float s = 0.f;
#pragma unroll
    for (int i = 0; i < 4; i++) {
        v[i].x = __expf(v[i].x - mx); s += v[i].x;
        v[i].y = __expf(v[i].y - mx); s += v[i].y;
        v[i].z = __expf(v[i].z - mx); s += v[i].z;
        v[i].w = __expf(v[i].w - mx); s += v[i].w;
    }
    s = warpRedSum(s);
    __syncthreads();
    if (lid == 0) red[wid] = s;
    __syncthreads();
    // FIX: identity 0 for lanes >= 8 (was red[lid&7] -> 4x overcount)
    s = (lid < 8) ? red[lid] : 0.f;
    s = warpRedSum(s);
    float rinv = 1.f / s;

#pragma unroll
    for (int i = 0; i < 4; i++) {
        v[i].x *= rinv; v[i].y *= rinv; v[i].z *= rinv; v[i].w *= rinv;
        p[t + i * 256] = v[i];
    }
}

// ---------------- launch ----------------
extern "C" void kernel_launch(void* const* d_in, const int* in_sizes, int n_in,
                              void* d_out, int out_size) {
    const float* x     = (const float*)d_in[0];
    const float* y     = (const float*)d_in[1];
    const float* w_qk  = (const float*)d_in[2];
    const float* w_v   = (const float*)d_in[3];
    const float* b_v   = (const float*)d_in[4];
    const float* w_t   = (const float*)d_in[5];
    const float* b_t   = (const float*)d_in[6];
    const float* gamma = (const float*)d_in[7];
    const float* beta  = (const float*)d_in[8];
    const float* rmean = (const float*)d_in[9];
    const float* rvar  = (const float*)d_in[10];
    float* out = (float*)d_out;

    float *q, *k, *v, *e, *o, *inv, *cadd;
    cudaGetSymbolAddress((void**)&q,    g_q);
    cudaGetSymbolAddress((void**)&k,    g_kmat);
    cudaGetSymbolAddress((void**)&v,    g_v);
    cudaGetSymbolAddress((void**)&e,    g_e);
    cudaGetSymbolAddress((void**)&o,    g_o);
    cudaGetSymbolAddress((void**)&inv,  g_inv);
    cudaGetSymbolAddress((void**)&cadd, g_cadd);

    const float scale = 0.088388347648318447f;  // 1/sqrt(128)

    precomp_k<<<1, 512>>>(gamma, beta, rmean, rvar, b_t);

    // q = w_qk @ x[b] : [128,512] x [512,4096]
    sgemm_k<0, 0, 0><<<dim3(NN / 128, DAD / 128, BSZ), 256>>>(
        w_qk, x, q, DAD, NN, CDIM, 0, (long long)CDIM * NN, (long long)DAD * NN,
        1.f, nullptr, nullptr, nullptr);

    // k = w_qk @ y[b]
    sgemm_k<0, 0, 0><<<dim3(MM / 128, DAD / 128, BSZ), 256>>>(
        w_qk, y, k, DAD, MM, CDIM, 0, (long long)CDIM * MM, (long long)DAD * MM,
        1.f, nullptr, nullptr, nullptr);

    // v = w_v @ y[b] + b_v : [512,512] x [512,4096]
    sgemm_k<0, 0, 1><<<dim3(MM / 128, CDIM / 128, BSZ), 256>>>(
        w_v, y, v, CDIM, MM, CDIM, 0, (long long)CDIM * MM, (long long)CDIM * MM,
        1.f, b_v, nullptr, nullptr);

    // e[n,m] = scale * sum_d q[d,n] k[d,m]  (A = q transposed-view, B = k)
    sgemm_k<1, 0, 0><<<dim3(MM / 128, NN / 128, BSZ), 256>>>(
        q, k, e, NN, MM, DAD, (long long)DAD * NN, (long long)DAD * MM,
        (long long)NN * MM, scale, nullptr, nullptr, nullptr);

    // softmax over m (rows of 4096)
    softmax_k<<<BSZ * NN, 256>>>(e);

    // o[n,c] = sum_m attn[n,m] v[c,m]  (B transposed-view of v)
    sgemm_k<0, 1, 0><<<dim3(CDIM / 128, NN / 128, BSZ), 256>>>(
        e, v, o, NN, CDIM, MM, (long long)NN * MM, (long long)CDIM * MM,
        (long long)NN * CDIM, 1.f, nullptr, nullptr, nullptr);

    // out[bn,co] = relu( (sum_c o[bn,c] w_t[co,c]) * inv[co] + cadd[co] )
    sgemm_k<0, 1, 2><<<dim3(CDIM / 128, (BSZ * NN) / 128, 1), 256>>>(
        o, w_t, out, BSZ * NN, CDIM, CDIM, 0, 0, 0,
        1.f, nullptr, inv, cadd);
}

// round 3
// speedup vs baseline: 3.6290x; 3.6290x over previous
#include <cuda_runtime.h>
#include <cuda_fp16.h>
#include <mma.h>
#include <math.h>
using namespace nvcuda;

#define BSZ 4
#define CDIM 512
#define NN 4096
#define MM 4096
#define DAD 128

#define BM 128
#define BN 128
#define BK 32
#define LDA_S 48    // halves, pad for smem
#define LDB_S 136   // halves
#define LDE_S 68    // floats, epilogue buffer

// ---------------- scratch (device globals; no allocation) ----------------
__device__ __half g_q[BSZ * DAD * NN];          // [B,128,4096]
__device__ __half g_kx[BSZ * DAD * MM];         // [B,128,4096]
__device__ __half g_v[BSZ * CDIM * MM];         // [B,512,4096]
__device__ float  g_e[(size_t)BSZ * NN * MM];   // [B,4096,4096] fp32
__device__ __half g_attn[(size_t)BSZ * NN * MM];// [B,4096,4096] half
__device__ __half g_o[BSZ * NN * CDIM];         // [B,4096,512]
__device__ float  g_inv[CDIM];
__device__ float  g_cadd[CDIM];

// ---------------- BN-fold precompute ----------------
__global__ void precomp_k(const float* __restrict__ gamma,
                          const float* __restrict__ beta,
                          const float* __restrict__ rmean,
                          const float* __restrict__ rvar,
                          const float* __restrict__ b_t) {
    int c = threadIdx.x;
    if (c < CDIM) {
        float inv = gamma[c] * rsqrtf(rvar[c] + 1e-5f);
        g_inv[c]  = inv;
        g_cadd[c] = b_t[c] * inv + beta[c] - rmean[c] * inv;
    }
}

// ---------------- tensor-core GEMM (fp16 in, fp32 accum) ----------------
// C[m,n] = epi( sum_k A[m,k]*B[k,n] )
// TA=1: A stored [K,M] row-major (lda=Mdim), else [M,K] (lda=Kdim)
// TB=1: B stored [N,K] row-major (ldb=Kdim), else [K,N] (ldb=Ndim)
// AT/BT: float (converted to half while staging) or __half (copied)
// EPI: 0 plain ; 1 +biasRow[m] ; 2 *alpha ; 4 relu(v*scaleCol[n]+addCol[n])
template <int TA, typename AT, int TB, typename BT, int EPI, typename CT>
__global__ __launch_bounds__(256)
void hgemm_k(const AT* __restrict__ Ag, const BT* __restrict__ Bg,
             CT* __restrict__ Cg,
             int Mdim, int Ndim, int Kdim,
             long long sA, long long sB, long long sC,
             float alpha,
             const float* __restrict__ biasRow,
             const float* __restrict__ scaleCol,
             const float* __restrict__ addCol) {
    __shared__ __align__(16) char smem_raw[34816];
    __half* As = (__half*)smem_raw;                 // [BM][LDA_S]
    __half* Bs = (__half*)(smem_raw + BM * LDA_S * 2); // [BK][LDB_S]
    float*  Es = (float*)smem_raw;                  // [8][16][LDE_S]

    const AT* A = Ag + (long long)blockIdx.z * sA;
    const BT* B = Bg + (long long)blockIdx.z * sB;
    CT*       C = Cg + (long long)blockIdx.z * sC;

    const int row0 = blockIdx.y * BM;
    const int col0 = blockIdx.x * BN;
    const int t = threadIdx.x;
    const int lda = TA ? Mdim : Kdim;
    const int ldb = TB ? Kdim : Ndim;
    const int w = t >> 5, lane = t & 31;
    const int wm0 = (w >> 1) * 32;   // 4 warp-rows
    const int wn0 = (w & 1) * 64;    // 2 warp-cols

    wmma::fragment<wmma::accumulator, 16, 16, 16, float> cf[2][4];
#pragma unroll
    for (int i = 0; i < 2; i++)
#pragma unroll
        for (int j = 0; j < 4; j++) wmma::fill_fragment(cf[i][j], 0.0f);

    for (int k0 = 0; k0 < Kdim; k0 += BK) {
        // ---------- stage A ----------
        if constexpr (TA == 0) {
            if constexpr (sizeof(AT) == 4) {
#pragma unroll
                for (int c = t; c < BM * (BK / 4); c += 256) {
                    int m = c >> 3, k4 = (c & 7) << 2;
                    float4 v = *(const float4*)((const float*)A +
                               (long long)(row0 + m) * lda + k0 + k4);
                    __half* d = As + m * LDA_S + k4;
                    d[0] = __float2half_rn(v.x); d[1] = __float2half_rn(v.y);
                    d[2] = __float2half_rn(v.z); d[3] = __float2half_rn(v.w);
                }
            } else {
#pragma unroll
                for (int c = t; c < BM * (BK / 8); c += 256) {
                    int m = c >> 2, k8 = (c & 3) << 3;
                    uint4 v = *(const uint4*)((const __half*)A +
                              (long long)(row0 + m) * lda + k0 + k8);
                    *(uint4*)(As + m * LDA_S + k8) = v;
                }
            }
        } else {  // A stored [K, M]
            if constexpr (sizeof(AT) == 4) {
#pragma unroll
                for (int c = t; c < BK * (BM / 4); c += 256) {
                    int k = c >> 5, m4 = (c & 31) << 2;
                    float4 v = *(const float4*)((const float*)A +
                               (long long)(k0 + k) * lda + row0 + m4);
                    As[(m4 + 0) * LDA_S + k] = __float2half_rn(v.x);
                    As[(m4 + 1) * LDA_S + k] = __float2half_rn(v.y);
                    As[(m4 + 2) * LDA_S + k] = __float2half_rn(v.z);
                    As[(m4 + 3) * LDA_S + k] = __float2half_rn(v.w);
                }
            } else {
#pragma unroll
                for (int c = t; c < BK * (BM / 8); c += 256) {
                    int k = c >> 4, m8 = (c & 15) << 3;
                    uint4 v = *(const uint4*)((const __half*)A +
                              (long long)(k0 + k) * lda + row0 + m8);
                    __half h[8]; *(uint4*)h = v;
#pragma unroll
                    for (int i = 0; i < 8; i++) As[(m8 + i) * LDA_S + k] = h[i];
                }
            }
        }
        // ---------- stage B ----------
        if constexpr (TB == 0) {
            if constexpr (sizeof(BT) == 4) {
#pragma unroll
                for (int c = t; c < BK * (BN / 4); c += 256) {
                    int k = c >> 5, n4 = (c & 31) << 2;
                    float4 v = *(const float4*)((const float*)B +
                               (long long)(k0 + k) * ldb + col0 + n4);
                    __half* d = Bs + k * LDB_S + n4;
                    d[0] = __float2half_rn(v.x); d[1] = __float2half_rn(v.y);
                    d[2] = __float2half_rn(v.z); d[3] = __float2half_rn(v.w);
                }
            } else {
#pragma unroll
                for (int c = t; c < BK * (BN / 8); c += 256) {
                    int k = c >> 4, n8 = (c & 15) << 3;
                    uint4 v = *(const uint4*)((const __half*)B +
                              (long long)(k0 + k) * ldb + col0 + n8);
                    *(uint4*)(Bs + k * LDB_S + n8) = v;
                }
            }
        } else {  // B stored [N, K]
            if constexpr (sizeof(BT) == 4) {
#pragma unroll
                for (int c = t; c < BN * (BK / 4); c += 256) {
                    int n = c >> 3, k4 = (c & 7) << 2;
                    float4 v = *(const float4*)((const float*)B +
                               (long long)(col0 + n) * ldb + k0 + k4);
                    Bs[(k4 + 0) * LDB_S + n] = __float2half_rn(v.x);
                    Bs[(k4 + 1) * LDB_S + n] = __float2half_rn(v.y);
                    Bs[(k4 + 2) * LDB_S + n] = __float2half_rn(v.z);
                    Bs[(k4 + 3) * LDB_S + n] = __float2half_rn(v.w);
                }
            } else {
#pragma unroll
                for (int c = t; c < BN * (BK / 8); c += 256) {
                    int n = c >> 2, k8 = (c & 3) << 3;
                    uint4 v = *(const uint4*)((const __half*)B +
                              (long long)(col0 + n) * ldb + k0 + k8);
                    __half h[8]; *(uint4*)h = v;
#pragma unroll
                    for (int i = 0; i < 8; i++) Bs[(k8 + i) * LDB_S + n] = h[i];
                }
            }
        }
        __syncthreads();

        // ---------- MMA ----------
#pragma unroll
        for (int ks = 0; ks < BK; ks += 16) {
            wmma::fragment<wmma::matrix_b, 16, 16, 16, __half, wmma::row_major> bf[4];
#pragma unroll
            for (int j = 0; j < 4; j++)
                wmma::load_matrix_sync(bf[j], Bs + ks * LDB_S + wn0 + j * 16, LDB_S);
#pragma unroll
            for (int mi = 0; mi < 2; mi++) {
                wmma::fragment<wmma::matrix_a, 16, 16, 16, __half, wmma::row_major> af;
                wmma::load_matrix_sync(af, As + (wm0 + mi * 16) * LDA_S + ks, LDA_S);
#pragma unroll
                for (int j = 0; j < 4; j++)
                    wmma::mma_sync(cf[mi][j], af, bf[j], cf[mi][j]);
            }
        }
        __syncthreads();
    }

    // ---------- epilogue via per-warp smem buffer ----------
    float* ep = Es + w * 16 * LDE_S;
#pragma unroll
    for (int mi = 0; mi < 2; mi++) {
#pragma unroll
        for (int j = 0; j < 4; j++)
            wmma::store_matrix_sync(ep + j * 16, cf[mi][j], LDE_S, wmma::mem_row_major);
        __syncwarp();
#pragma unroll
        for (int it = 0; it < 8; it++) {
            int idx = it * 32 + lane;          // 0..255 over 16 rows x 16 float4
            int r = idx >> 4, c4 = (idx & 15) << 2;
            float4 v = *(float4*)(ep + r * LDE_S + c4);
            int gr = row0 + wm0 + mi * 16 + r;
            int gc = col0 + wn0 + c4;
            if constexpr (EPI == 1) {
                float bb = biasRow[gr];
                v.x += bb; v.y += bb; v.z += bb; v.w += bb;
            }
            if constexpr (EPI == 2) {
                v.x *= alpha; v.y *= alpha; v.z *= alpha; v.w *= alpha;
            }
            if constexpr (EPI == 4) {
                v.x = fmaxf(fmaf(v.x, scaleCol[gc + 0], addCol[gc + 0]), 0.f);
                v.y = fmaxf(fmaf(v.y, scaleCol[gc + 1], addCol[gc + 1]), 0.f);
                v.z = fmaxf(fmaf(v.z, scaleCol[gc + 2], addCol[gc + 2]), 0.f);
                v.w = fmaxf(fmaf(v.w, scaleCol[gc + 3], addCol[gc + 3]), 0.f);
            }
            if constexpr (sizeof(CT) == 2) {
                __half h[4] = { __float2half_rn(v.x), __float2half_rn(v.y),
                                __float2half_rn(v.z), __float2half_rn(v.w) };
                *(uint2*)((__half*)C + (long long)gr * Ndim + gc) = *(uint2*)h;
            } else {
                *(float4*)((float*)C + (long long)gr * Ndim + gc) = v;
            }
        }
        __syncwarp();
    }
}

// ---------------- row softmax: e (fp32) -> attn (half) ----------------
__inline__ __device__ float warpRedMax(float v) {
#pragma unroll
    for (int o = 16; o; o >>= 1) v = fmaxf(v, __shfl_xor_sync(0xFFFFFFFFu, v, o));
    return v;
}
__inline__ __device__ float warpRedSum(float v) {
#pragma unroll
    for (int o = 16; o; o >>= 1) v += __shfl_xor_sync(0xFFFFFFFFu, v, o);
    return v;
}

__global__ __launch_bounds__(256) void softmax_k(const float* __restrict__ e,
                                                 __half* __restrict__ attn) {
    __shared__ float red[8];
    size_t row = blockIdx.x;
    const float4* p = (const float4*)(e + row * 4096);
    uint2* pout = (uint2*)(attn + row * 4096);
    int t = threadIdx.x;
    int wid = t >> 5, lid = t & 31;

    float4 v[4];
    float mx = -1e30f;
#pragma unroll
    for (int i = 0; i < 4; i++) {
        v[i] = p[t + i * 256];
        mx = fmaxf(mx, fmaxf(fmaxf(v[i].x, v[i].y), fmaxf(v[i].z, v[i].w)));
    }
    mx = warpRedMax(mx);
    if (lid == 0) red[wid] = mx;
    __syncthreads();
    mx = (lid < 8) ? red[lid] : -1e30f;
    mx = warpRedMax(mx);

    float s = 0.f;
#pragma unroll
    for (int i = 0; i < 4; i++) {
        v[i].x = __expf(v[i].x - mx); s += v[i].x;
        v[i].y = __expf(v[i].y - mx); s += v[i].y;
        v[i].z = __expf(v[i].z - mx); s += v[i].z;
        v[i].w = __expf(v[i].w - mx); s += v[i].w;
    }
    s = warpRedSum(s);
    __syncthreads();
    if (lid == 0) red[wid] = s;
    __syncthreads();
    s = (lid < 8) ? red[lid] : 0.f;
    s = warpRedSum(s);
    float rinv = 1.f / s;

#pragma unroll
    for (int i = 0; i < 4; i++) {
        __half h[4] = { __float2half_rn(v[i].x * rinv), __float2half_rn(v[i].y * rinv),
                        __float2half_rn(v[i].z * rinv), __float2half_rn(v[i].w * rinv) };
        pout[t + i * 256] = *(uint2*)h;
    }
}

// ---------------- launch ----------------
extern "C" void kernel_launch(void* const* d_in, const int* in_sizes, int n_in,
                              void* d_out, int out_size) {
    const float* x     = (const float*)d_in[0];
    const float* y     = (const float*)d_in[1];
    const float* w_qk  = (const float*)d_in[2];
    const float* w_v   = (const float*)d_in[3];
    const float* b_v   = (const float*)d_in[4];
    const float* w_t   = (const float*)d_in[5];
    const float* b_t   = (const float*)d_in[6];
    const float* gamma = (const float*)d_in[7];
    const float* beta  = (const float*)d_in[8];
    const float* rmean = (const float*)d_in[9];
    const float* rvar  = (const float*)d_in[10];
    float* out = (float*)d_out;

    __half *q, *k, *v, *attn, *o;
    float *e, *inv, *cadd;
    cudaGetSymbolAddress((void**)&q,    g_q);
    cudaGetSymbolAddress((void**)&k,    g_kx);
    cudaGetSymbolAddress((void**)&v,    g_v);
    cudaGetSymbolAddress((void**)&e,    g_e);
    cudaGetSymbolAddress((void**)&attn, g_attn);
    cudaGetSymbolAddress((void**)&o,    g_o);
    cudaGetSymbolAddress((void**)&inv,  g_inv);
    cudaGetSymbolAddress((void**)&cadd, g_cadd);

    const float scale = 0.088388347648318447f;  // 1/sqrt(128)

    precomp_k<<<1, 512>>>(gamma, beta, rmean, rvar, b_t);

    // q = w_qk @ x : [128,512]x[512,4096] -> half
    hgemm_k<0, float, 0, float, 0, __half><<<dim3(NN / BN, DAD / BM, BSZ), 256>>>(
        w_qk, x, q, DAD, NN, CDIM, 0, (long long)CDIM * NN, (long long)DAD * NN,
        1.f, nullptr, nullptr, nullptr);

    // k = w_qk @ y -> half
    hgemm_k<0, float, 0, float, 0, __half><<<dim3(MM / BN, DAD / BM, BSZ), 256>>>(
        w_qk, y, k, DAD, MM, CDIM, 0, (long long)CDIM * MM, (long long)DAD * MM,
        1.f, nullptr, nullptr, nullptr);

    // v = w_v @ y + b_v -> half
    hgemm_k<0, float, 0, float, 1, __half><<<dim3(MM / BN, CDIM / BM, BSZ), 256>>>(
        w_v, y, v, CDIM, MM, CDIM, 0, (long long)CDIM * MM, (long long)CDIM * MM,
        1.f, b_v, nullptr, nullptr);

    // e[n,m] = scale * sum_d q[d,n]k[d,m] : TA=1 (q is [K=128, M=4096]) -> fp32
    hgemm_k<1, __half, 0, __half, 2, float><<<dim3(MM / BN, NN / BM, BSZ), 256>>>(
        q, k, e, NN, MM, DAD, (long long)DAD * NN, (long long)DAD * MM,
        (long long)NN * MM, scale, nullptr, nullptr, nullptr);

    // softmax rows of 4096: e fp32 -> attn half
    softmax_k<<<BSZ * NN, 256>>>(e, attn);

    // o[n,c] = sum_m attn[n,m] v[c,m] : TB=1 (v is [N=512, K=4096]) -> half
    hgemm_k<0, __half, 1, __half, 0, __half><<<dim3(CDIM / BN, NN / BM, BSZ), 256>>>(
        attn, v, o, NN, CDIM, MM, (long long)NN * MM, (long long)CDIM * MM,
        (long long)NN * CDIM, 1.f, nullptr, nullptr, nullptr);

    // out[bn,co] = relu((sum_c o[bn,c] w_t[co,c]) * inv[co] + cadd[co]) -> fp32
    hgemm_k<0, __half, 1, float, 4, float><<<dim3(CDIM / BN, (BSZ * NN) / BM, 1), 256>>>(
        o, w_t, out, BSZ * NN, CDIM, CDIM, 0, 0, 0,
        1.f, nullptr, inv, cadd);
}

// round 5
// speedup vs baseline: 6.1361x; 1.6908x over previous
#include <cuda_runtime.h>
#include <cuda_fp16.h>
#include <mma.h>
#include <math.h>
#include <cstdint>
#include <type_traits>
using namespace nvcuda;

#define BSZ 4
#define CDIM 512
#define NN 4096
#define MM 4096
#define DAD 128

#define BM 128
#define BN 128
#define BK 32
// padded smem leading dims (halves); both are odd multiples of 8 -> conflict-friendly
#define LD_K  40    // rows of BK(+8)   : [*][k]
#define LD_MN 136   // rows of 128(+8)  : [*][m or n]

// ---------------- scratch (device globals; no allocation) ----------------
__device__ __half g_xh[BSZ * CDIM * NN];        // x as half
__device__ __half g_yh[BSZ * CDIM * MM];        // y as half
__device__ __half g_wqk[DAD * CDIM];
__device__ __half g_wv[CDIM * CDIM];
__device__ __half g_wt[CDIM * CDIM];
__device__ __half g_q[BSZ * DAD * NN];          // [B,128,4096]
__device__ __half g_kx[BSZ * DAD * MM];         // [B,128,4096]
__device__ __half g_v[BSZ * CDIM * MM];         // [B,512,4096]
__device__ __half g_e[(size_t)BSZ * NN * MM];   // energies, half
__device__ __half g_attn[(size_t)BSZ * NN * MM];// attn, half
__device__ __half g_o[BSZ * NN * CDIM];         // [B,4096,512]
__device__ float  g_inv[CDIM];
__device__ float  g_cadd[CDIM];

// ---------------- helpers ----------------
__device__ __forceinline__ void cp_async16(void* smem, const void* gmem) {
    unsigned s = (unsigned)__cvta_generic_to_shared(smem);
    asm volatile("cp.async.cg.shared.global [%0], [%1], 16;\n" :: "r"(s), "l"(gmem));
}
__device__ __forceinline__ void cp_commit() {
    asm volatile("cp.async.commit_group;\n");
}
__device__ __forceinline__ void cp_wait_all() {
    asm volatile("cp.async.wait_group 0;\n");
}

// ---------------- fp32 -> fp16 convert ----------------
__global__ void f2h_k(const float* __restrict__ in, __half* __restrict__ out, int n4) {
    int i = blockIdx.x * blockDim.x + threadIdx.x;
    if (i < n4) {
        float4 v = ((const float4*)in)[i];
        __half h[4] = { __float2half_rn(v.x), __float2half_rn(v.y),
                        __float2half_rn(v.z), __float2half_rn(v.w) };
        ((uint2*)out)[i] = *(uint2*)h;
    }
}

// ---------------- BN-fold precompute ----------------
__global__ void precomp_k(const float* __restrict__ gamma,
                          const float* __restrict__ beta,
                          const float* __restrict__ rmean,
                          const float* __restrict__ rvar,
                          const float* __restrict__ b_t) {
    int c = threadIdx.x;
    if (c < CDIM) {
        float inv = gamma[c] * rsqrtf(rvar[c] + 1e-5f);
        g_inv[c]  = inv;
        g_cadd[c] = b_t[c] * inv + beta[c] - rmean[c] * inv;
    }
}

// ---------------- pipelined tensor-core GEMM (half in, fp32 accum) ----------------
// C[m,n] = epi( sum_k A[m,k]*B[k,n] )
// TA=1: A stored [K,M] (lda=Mdim) -> smem As[k][m], col_major frag
// TA=0: A stored [M,K] (lda=Kdim) -> smem As[m][k], row_major frag
// TB=1: B stored [N,K] (ldb=Kdim) -> smem Bs[n][k], col_major frag
// TB=0: B stored [K,N] (ldb=Ndim) -> smem Bs[k][n], row_major frag
// EPI: 0 plain ; 1 +biasRow[m] ; 2 *alpha ; 4 relu(v*scaleCol[n]+addCol[n])
template <int TA, int TB, int EPI, typename CT>
__global__ __launch_bounds__(256)
void hgemm_k(const __half* __restrict__ Ag, const __half* __restrict__ Bg,
             CT* __restrict__ Cg,
             int Mdim, int Ndim, int Kdim,
             long long sA, long long sB, long long sC,
             float alpha,
             const float* __restrict__ biasRow,
             const float* __restrict__ scaleCol,
             const float* __restrict__ addCol) {
    constexpr int A_HALVES = TA ? BK * LD_MN : BM * LD_K;   // per stage
    constexpr int B_HALVES = TB ? BN * LD_K  : BK * LD_MN;
    constexpr int STAGE = A_HALVES + B_HALVES;
    __shared__ __align__(16) __half smem[2 * STAGE];
    float* Es = (float*)smem;   // epilogue reuse: 8*16*68*4 = 34816 B <= 2*STAGE*2

    const __half* A = Ag + (long long)blockIdx.z * sA;
    const __half* B = Bg + (long long)blockIdx.z * sB;
    CT*           C = Cg + (long long)blockIdx.z * sC;

    const int row0 = blockIdx.y * BM;
    const int col0 = blockIdx.x * BN;
    const int t = threadIdx.x;
    const int lda = TA ? Mdim : Kdim;
    const int ldb = TB ? Kdim : Ndim;
    const int w = t >> 5, lane = t & 31;
    const int wm0 = (w >> 1) * 32;   // 4 warp-rows of 32
    const int wn0 = (w & 1) * 64;    // 2 warp-cols of 64

    using AMaj = typename std::conditional<TA == 0, wmma::row_major, wmma::col_major>::type;
    using BMaj = typename std::conditional<TB == 0, wmma::row_major, wmma::col_major>::type;

    wmma::fragment<wmma::accumulator, 16, 16, 16, float> cf[2][4];
#pragma unroll
    for (int i = 0; i < 2; i++)
#pragma unroll
        for (int j = 0; j < 4; j++) wmma::fill_fragment(cf[i][j], 0.0f);

    // issue one k-tile's copies into the given stage
    auto issue = [&](int k0, int stg) {
        __half* As = smem + stg * STAGE;
        __half* Bs = As + A_HALVES;
        // A: 512 chunks of 8 halves (16B)
#pragma unroll
        for (int i = 0; i < 2; i++) {
            int c = t + i * 256;
            if constexpr (TA == 0) {
                int m = c >> 2, kc = (c & 3) << 3;        // BK/8 = 4
                cp_async16(As + m * LD_K + kc,
                           A + (long long)(row0 + m) * lda + k0 + kc);
            } else {
                int k = c >> 4, mc = (c & 15) << 3;       // BM/8 = 16
                cp_async16(As + k * LD_MN + mc,
                           A + (long long)(k0 + k) * lda + row0 + mc);
            }
        }
        // B: 512 chunks
#pragma unroll
        for (int i = 0; i < 2; i++) {
            int c = t + i * 256;
            if constexpr (TB == 0) {
                int k = c >> 4, nc = (c & 15) << 3;       // BN/8 = 16
                cp_async16(Bs + k * LD_MN + nc,
                           B + (long long)(k0 + k) * ldb + col0 + nc);
            } else {
                int n = c >> 2, kc = (c & 3) << 3;        // BK/8 = 4
                cp_async16(Bs + n * LD_K + kc,
                           B + (long long)(col0 + n) * ldb + k0 + kc);
            }
        }
        cp_commit();
    };

    const int T = Kdim / BK;
    issue(0, 0);
    for (int it = 0; it < T; it++) {
        cp_wait_all();
        __syncthreads();
        if (it + 1 < T) issue((it + 1) * BK, (it + 1) & 1);

        const __half* As = smem + (it & 1) * STAGE;
        const __half* Bs = As + A_HALVES;
#pragma unroll
        for (int ks = 0; ks < BK; ks += 16) {
            wmma::fragment<wmma::matrix_b, 16, 16, 16, __half, BMaj> bf[4];
#pragma unroll
            for (int j = 0; j < 4; j++) {
                const __half* pB = TB ? Bs + (wn0 + j * 16) * LD_K + ks
                                      : Bs + ks * LD_MN + wn0 + j * 16;
                wmma::load_matrix_sync(bf[j], pB, TB ? LD_K : LD_MN);
            }
#pragma unroll
            for (int mi = 0; mi < 2; mi++) {
                wmma::fragment<wmma::matrix_a, 16, 16, 16, __half, AMaj> af;
                const __half* pA = TA ? As + ks * LD_MN + wm0 + mi * 16
                                      : As + (wm0 + mi * 16) * LD_K + ks;
                wmma::load_matrix_sync(af, pA, TA ? LD_MN : LD_K);
#pragma unroll
                for (int j = 0; j < 4; j++)
                    wmma::mma_sync(cf[mi][j], af, bf[j], cf[mi][j]);
            }
        }
        __syncthreads();
    }

    // ---------- epilogue via per-warp smem buffer ----------
    float* ep = Es + w * 16 * 68;
#pragma unroll
    for (int mi = 0; mi < 2; mi++) {
#pragma unroll
        for (int j = 0; j < 4; j++)
            wmma::store_matrix_sync(ep + j * 16, cf[mi][j], 68, wmma::mem_row_major);
        __syncwarp();
#pragma unroll
        for (int it = 0; it < 8; it++) {
            int idx = it * 32 + lane;
            int r = idx >> 4, c4 = (idx & 15) << 2;
            float4 v = *(float4*)(ep + r * 68 + c4);
            int gr = row0 + wm0 + mi * 16 + r;
            int gc = col0 + wn0 + c4;
            if constexpr (EPI == 1) {
                float bb = biasRow[gr];
                v.x += bb; v.y += bb; v.z += bb; v.w += bb;
            }
            if constexpr (EPI == 2) {
                v.x *= alpha; v.y *= alpha; v.z *= alpha; v.w *= alpha;
            }
            if constexpr (EPI == 4) {
                v.x = fmaxf(fmaf(v.x, scaleCol[gc + 0], addCol[gc + 0]), 0.f);
                v.y = fmaxf(fmaf(v.y, scaleCol[gc + 1], addCol[gc + 1]), 0.f);
                v.z = fmaxf(fmaf(v.z, scaleCol[gc + 2], addCol[gc + 2]), 0.f);
                v.w = fmaxf(fmaf(v.w, scaleCol[gc + 3], addCol[gc + 3]), 0.f);
            }
            if constexpr (sizeof(CT) == 2) {
                __half h[4] = { __float2half_rn(v.x), __float2half_rn(v.y),
                                __float2half_rn(v.z), __float2half_rn(v.w) };
                *(uint2*)((__half*)C + (long long)gr * Ndim + gc) = *(uint2*)h;
            } else {
                *(float4*)((float*)C + (long long)gr * Ndim + gc) = v;
            }
        }
        __syncwarp();
    }
}

// ---------------- row softmax: e (half) -> attn (half) ----------------
__inline__ __device__ float warpRedMax(float v) {
#pragma unroll
    for (int o = 16; o; o >>= 1) v = fmaxf(v, __shfl_xor_sync(0xFFFFFFFFu, v, o));
    return v;
}
__inline__ __device__ float warpRedSum(float v) {
#pragma unroll
    for (int o = 16; o; o >>= 1) v += __shfl_xor_sync(0xFFFFFFFFu, v, o);
    return v;
}

__global__ __launch_bounds__(256) void softmax_k(const __half* __restrict__ e,
                                                 __half* __restrict__ attn) {
    __shared__ float red[8];
    size_t row = blockIdx.x;
    const uint4* p = (const uint4*)(e + row * 4096);   // 512 uint4 per row
    uint4* pout = (uint4*)(attn + row * 4096);
    int t = threadIdx.x;
    int wid = t >> 5, lid = t & 31;

    float f[16];
    float mx = -1e30f;
#pragma unroll
    for (int i = 0; i < 2; i++) {
        uint4 u = p[t + i * 256];
        __half h[8]; *(uint4*)h = u;
#pragma unroll
        for (int j = 0; j < 8; j++) {
            f[i * 8 + j] = __half2float(h[j]);
            mx = fmaxf(mx, f[i * 8 + j]);
        }
    }
    mx = warpRedMax(mx);
    if (lid == 0) red[wid] = mx;
    __syncthreads();
    mx = (lid < 8) ? red[lid] : -1e30f;
    mx = warpRedMax(mx);

    float s = 0.f;
#pragma unroll
    for (int i = 0; i < 16; i++) { f[i] = __expf(f[i] - mx); s += f[i]; }
    s = warpRedSum(s);
    __syncthreads();
    if (lid == 0) red[wid] = s;
    __syncthreads();
    s = (lid < 8) ? red[lid] : 0.f;
    s = warpRedSum(s);
    float rinv = 1.f / s;

#pragma unroll
    for (int i = 0; i < 2; i++) {
        __half h[8];
#pragma unroll
        for (int j = 0; j < 8; j++) h[j] = __float2half_rn(f[i * 8 + j] * rinv);
        pout[t + i * 256] = *(uint4*)h;
    }
}

// ---------------- launch ----------------
extern "C" void kernel_launch(void* const* d_in, const int* in_sizes, int n_in,
                              void* d_out, int out_size) {
    const float* x     = (const float*)d_in[0];
    const float* y     = (const float*)d_in[1];
    const float* w_qk  = (const float*)d_in[2];
    const float* w_v   = (const float*)d_in[3];
    const float* b_v   = (const float*)d_in[4];
    const float* w_t   = (const float*)d_in[5];
    const float* b_t   = (const float*)d_in[6];
    const float* gamma = (const float*)d_in[7];
    const float* beta  = (const float*)d_in[8];
    const float* rmean = (const float*)d_in[9];
    const float* rvar  = (const float*)d_in[10];
    float* out = (float*)d_out;

    __half *xh, *yh, *wqk, *wv, *wt, *q, *k, *v, *e, *attn, *o;
    float *inv, *cadd;
    cudaGetSymbolAddress((void**)&xh,   g_xh);
    cudaGetSymbolAddress((void**)&yh,   g_yh);
    cudaGetSymbolAddress((void**)&wqk,  g_wqk);
    cudaGetSymbolAddress((void**)&wv,   g_wv);
    cudaGetSymbolAddress((void**)&wt,   g_wt);
    cudaGetSymbolAddress((void**)&q,    g_q);
    cudaGetSymbolAddress((void**)&k,    g_kx);
    cudaGetSymbolAddress((void**)&v,    g_v);
    cudaGetSymbolAddress((void**)&e,    g_e);
    cudaGetSymbolAddress((void**)&attn, g_attn);
    cudaGetSymbolAddress((void**)&o,    g_o);
    cudaGetSymbolAddress((void**)&inv,  g_inv);
    cudaGetSymbolAddress((void**)&cadd, g_cadd);

    const float scale = 0.088388347648318447f;  // 1/sqrt(128)

    // fp32 -> fp16 conversions
    {
        int n4 = BSZ * CDIM * NN / 4;
        f2h_k<<<(n4 + 255) / 256, 256>>>(x, xh, n4);
        f2h_k<<<(n4 + 255) / 256, 256>>>(y, yh, n4);
        int w4a = DAD * CDIM / 4;
        f2h_k<<<(w4a + 255) / 256, 256>>>(w_qk, wqk, w4a);
        int w4b = CDIM * CDIM / 4;
        f2h_k<<<(w4b + 255) / 256, 256>>>(w_v, wv, w4b);
        f2h_k<<<(w4b + 255) / 256, 256>>>(w_t, wt, w4b);
    }
    precomp_k<<<1, 512>>>(gamma, beta, rmean, rvar, b_t);

    // q = w_qk @ x : [128,512]x[512,4096] -> half
    hgemm_k<0, 0, 0, __half><<<dim3(NN / BN, DAD / BM, BSZ), 256>>>(
        wqk, xh, q, DAD, NN, CDIM, 0, (long long)CDIM * NN, (long long)DAD * NN,
        1.f, nullptr, nullptr, nullptr);

    // k = w_qk @ y -> half
    hgemm_k<0, 0, 0, __half><<<dim3(MM / BN, DAD / BM, BSZ), 256>>>(
        wqk, yh, k, DAD, MM, CDIM, 0, (long long)CDIM * MM, (long long)DAD * MM,
        1.f, nullptr, nullptr, nullptr);

    // v = w_v @ y + b_v -> half
    hgemm_k<0, 0, 1, __half><<<dim3(MM / BN, CDIM / BM, BSZ), 256>>>(
        wv, yh, v, CDIM, MM, CDIM, 0, (long long)CDIM * MM, (long long)CDIM * MM,
        1.f, b_v, nullptr, nullptr);

    // e[n,m] = scale * sum_d q[d,n]k[d,m] : TA=1 (q is [K=128, M=4096]) -> half
    hgemm_k<1, 0, 2, __half><<<dim3(MM / BN, NN / BM, BSZ), 256>>>(
        q, k, e, NN, MM, DAD, (long long)DAD * NN, (long long)DAD * MM,
        (long long)NN * MM, scale, nullptr, nullptr, nullptr);

    // softmax rows of 4096: e half -> attn half
    softmax_k<<<BSZ * NN, 256>>>(e, attn);

    // o[n,c] = sum_m attn[n,m] v[c,m] : TB=1 (v is [N=512, K=4096]) -> half
    hgemm_k<0, 1, 0, __half><<<dim3(CDIM / BN, NN / BM, BSZ), 256>>>(
        attn, v, o, NN, CDIM, MM, (long long)NN * MM, (long long)CDIM * MM,
        (long long)NN * CDIM, 1.f, nullptr, nullptr, nullptr);

    // out[bn,co] = relu((sum_c o[bn,c] w_t[co,c]) * inv[co] + cadd[co]) -> fp32
    hgemm_k<0, 1, 4, float><<<dim3(CDIM / BN, (BSZ * NN) / BM, 1), 256>>>(
        o, wt, out, BSZ * NN, CDIM, CDIM, 0, 0, 0,
        1.f, nullptr, inv, cadd);
}